// round 7
// baseline (speedup 1.0000x reference)
#include <cuda_runtime.h>
#include <cuda_bf16.h>

#define N_NODES 50000
#define N_EDGES 800000
#define STEPS 10
#define NEG_SLOPE 0.01f
#define LN_EPS 1e-5f

#define ENC_EDGE_BLOCKS 3125              // 3125*256 = 800000
#define ENC_NODE_BLOCKS 1184
#define EDGE_BLOCKS 592
#define EDGE_WARPS (EDGE_BLOCKS * 8)      // 4736
#define EDGE_CHUNK ((N_EDGES + EDGE_WARPS - 1) / EDGE_WARPS)   // 169
#define NODE_BLOCKS 592

// ---------------- device scratch (no allocation allowed) ----------------
__device__ float g_h  [N_NODES * 32];
__device__ float g_e  [N_EDGES * 32];     // receiver-sorted
__device__ float g_hs [N_NODES * 32];
__device__ float g_hd [N_NODES * 32];
__device__ float g_agg[N_NODES * 32];     // segment sums; consumer zeroes after use
__device__ float g_inv[N_NODES];
__device__ int   g_hist[N_NODES];         // zero-init; re-zeroed inside fused_encode each replay
__device__ int   g_off [N_NODES + 1];
__device__ int   g_cursor[N_NODES];
__device__ int   g_snd_s[N_EDGES];
__device__ int   g_rcv_s[N_EDGES];

__device__ __forceinline__ float leaky(float v) {
    return v >= 0.f ? v : NEG_SLOPE * v;
}

// ================= launch 1: in-degree histogram =================
__global__ void hist_edges(const int* __restrict__ rcv) {
    int i = blockIdx.x * blockDim.x + threadIdx.x;
    if (i < N_EDGES) atomicAdd(&g_hist[rcv[i]], 1);
}

// ================= launch 2: single-block full scan -> off/cursor/inv =================
__global__ void scan_all() {
    __shared__ int sh[1024];
    int tid = threadIdx.x;
    int base = 0;
    const int nchunks = (N_NODES + 1023) / 1024;
    for (int c = 0; c < nchunks; c++) {
        __syncthreads();
        int i = c * 1024 + tid;
        int v = (i < N_NODES) ? g_hist[i] : 0;
        sh[tid] = v;
        __syncthreads();
#pragma unroll
        for (int d = 1; d < 1024; d <<= 1) {
            int t = (tid >= d) ? sh[tid - d] : 0;
            __syncthreads();
            sh[tid] += t;
            __syncthreads();
        }
        if (i < N_NODES) {
            int off = base + sh[tid] - v;
            g_off[i] = off;
            g_cursor[i] = off;
            g_inv[i] = 1.f / fmaxf((float)v, 1.f);
        }
        base += sh[1023];
    }
    if (tid == 0) g_off[N_NODES] = base;   // == N_EDGES
}

// ================= launch 3: fused scatter + encoders + node_pre(step0) + agg zero =========
__global__ void __launch_bounds__(256) fused_encode(
        const float* __restrict__ ea, const int* __restrict__ snd, const int* __restrict__ rcv,
        const float* __restrict__ eeW, const float* __restrict__ eeb,
        const float* __restrict__ x, const float* __restrict__ neW, const float* __restrict__ neb,
        const float* __restrict__ eW0) {
    __shared__ float sw[64 * 32];
    __shared__ float sw2[224];

    if (blockIdx.x < ENC_EDGE_BLOCKS) {
        if (threadIdx.x < 96) sw[threadIdx.x] = eeW[threadIdx.x];
        else if (threadIdx.x < 128) sw[threadIdx.x] = eeb[threadIdx.x - 96];
        __syncthreads();
        int i = blockIdx.x * 256 + threadIdx.x;
        if (i < N_EDGES) {
            int r = rcv[i], s = snd[i];
            int pos = atomicAdd(&g_cursor[r], 1);
            g_snd_s[pos] = s;
            g_rcv_s[pos] = r;
            float a0 = ea[i * 3 + 0], a1 = ea[i * 3 + 1], a2 = ea[i * 3 + 2];
            float4* dst = (float4*)&g_e[pos * 32];
#pragma unroll
            for (int c4 = 0; c4 < 8; c4++) {
                float4 v;
                v.x = leaky(sw[96 + c4 * 4 + 0] + a0 * sw[0 * 32 + c4 * 4 + 0] + a1 * sw[1 * 32 + c4 * 4 + 0] + a2 * sw[2 * 32 + c4 * 4 + 0]);
                v.y = leaky(sw[96 + c4 * 4 + 1] + a0 * sw[0 * 32 + c4 * 4 + 1] + a1 * sw[1 * 32 + c4 * 4 + 1] + a2 * sw[2 * 32 + c4 * 4 + 1]);
                v.z = leaky(sw[96 + c4 * 4 + 2] + a0 * sw[0 * 32 + c4 * 4 + 2] + a1 * sw[1 * 32 + c4 * 4 + 2] + a2 * sw[2 * 32 + c4 * 4 + 2]);
                v.w = leaky(sw[96 + c4 * 4 + 3] + a0 * sw[0 * 32 + c4 * 4 + 3] + a1 * sw[1 * 32 + c4 * 4 + 3] + a2 * sw[2 * 32 + c4 * 4 + 3]);
                dst[c4] = v;
            }
        }
    } else {
        for (int i = threadIdx.x; i < 2048; i += 256) sw[i] = eW0[32 * 32 + i];
        for (int i = threadIdx.x; i < 224; i += 256)
            sw2[i] = (i < 192) ? neW[i] : neb[i - 192];
        __syncthreads();
        int lane = threadIdx.x & 31;
        int nb = blockIdx.x - ENC_EDGE_BLOCKS;
        int warp = nb * 8 + (threadIdx.x >> 5);
        int nwarps = ENC_NODE_BLOCKS * 8;
        for (int n = warp; n < N_NODES; n += nwarps) {
            float a = sw2[192 + lane];
#pragma unroll
            for (int k = 0; k < 6; k++) a += x[n * 6 + k] * sw2[k * 32 + lane];
            float hv = leaky(a);
            g_h[n * 32 + lane] = hv;
            float aS = 0.f, aD = 0.f;
#pragma unroll
            for (int k = 0; k < 32; k++) {
                float t = __shfl_sync(0xffffffffu, hv, k);
                aS += t * sw[k * 32 + lane];
                aD += t * sw[(32 + k) * 32 + lane];
            }
            g_hs[n * 32 + lane] = aS;
            g_hd[n * 32 + lane] = aD;
            g_agg[n * 32 + lane] = 0.f;      // zero agg for step-0 edge_update
        }
        int gtid = nb * 256 + threadIdx.x;
        for (int i = gtid; i < N_NODES; i += ENC_NODE_BLOCKS * 256) g_hist[i] = 0;
    }
}

// ================= per-step: edge update + fused segmented aggregation =================
// Each warp owns a contiguous edge range; accumulates per-segment sums in registers and
// flushes ONE atomicAdd row per segment (boundary segments get partial flushes).
__global__ void __launch_bounds__(256, 6) edge_update(
        const float* __restrict__ eW, const float* __restrict__ eb,
        const float* __restrict__ lns, const float* __restrict__ lnb) {
    __shared__ float wT[32 * 36];     // wT[c*36 + k] = eW[k*32+c]; conflict-free LDS.128
    __shared__ float prm[96];
    for (int i = threadIdx.x; i < 1024; i += 256) {
        int k = i >> 5, c = i & 31;
        wT[c * 36 + k] = eW[i];
    }
    if (threadIdx.x < 32) {
        prm[threadIdx.x]      = eb[threadIdx.x];
        prm[32 + threadIdx.x] = lns[threadIdx.x];
        prm[64 + threadIdx.x] = lnb[threadIdx.x];
    }
    __syncthreads();
    int lane = threadIdx.x & 31;
    int warp = (blockIdx.x * blockDim.x + threadIdx.x) >> 5;
    int lo = warp * EDGE_CHUNK;
    if (lo >= N_EDGES) return;
    int hi = min(lo + EDGE_CHUNK, N_EDGES);
    float bias = prm[lane], sc = prm[32 + lane], bi = prm[64 + lane];
    const float* wrow = &wT[lane * 36];

    float run = 0.f;
    int   cur_r = g_rcv_s[lo];                   // uniform
    float ev    = g_e[lo * 32 + lane];           // prefetched row for e=lo
    int   s     = g_snd_s[lo];

    for (int e = lo; e < hi; e++) {
        // ---- prefetch next edge's row + sender (hide latency under compute) ----
        float ev_n = 0.f;
        int   s_n = 0, r_n = -1;
        if (e + 1 < hi) {
            ev_n = g_e[(e + 1) * 32 + lane];
            s_n  = g_snd_s[e + 1];
        }
        if (e + 1 < N_EDGES) r_n = g_rcv_s[e + 1];

        // ---- GEMV: uniform float4 reloads of row e (L1-hit; fetched last iteration) ----
        float a = bias + g_hs[s * 32 + lane] + g_hd[cur_r * 32 + lane];
        float b = 0.f;
#pragma unroll
        for (int k4 = 0; k4 < 8; k4++) {
            float4 u  = *(const float4*)&g_e[e * 32 + k4 * 4];
            float4 w4 = *(const float4*)&wrow[k4 * 4];
            a += u.x * w4.x;  b += u.y * w4.y;
            a += u.z * w4.z;  b += u.w * w4.w;
        }
        float m = leaky(a + b);
        float sm = m, qq = m * m;
#pragma unroll
        for (int d = 16; d; d >>= 1) {
            sm += __shfl_xor_sync(0xffffffffu, sm, d);
            qq += __shfl_xor_sync(0xffffffffu, qq, d);
        }
        float mu = sm * (1.f / 32.f);
        float var = fmaxf(qq * (1.f / 32.f) - mu * mu, 0.f);
        float en = ev + (m - mu) * rsqrtf(var + LN_EPS) * sc + bi;
        g_e[e * 32 + lane] = en;
        run += en;

        // ---- segment flush (uniform across warp) ----
        if (e + 1 == hi || r_n != cur_r) {
            atomicAdd(&g_agg[cur_r * 32 + lane], run);
            run = 0.f;
            cur_r = r_n;
        }
        ev = ev_n;
        s  = s_n;
    }
}

// ================= per-step: node update (agg precomputed) + next-step Hs/Hd or decoder ====
__global__ void __launch_bounds__(256) node_update(
        const float* __restrict__ nW, const float* __restrict__ nb,
        const float* __restrict__ lns, const float* __restrict__ lnb,
        const float* __restrict__ eW_next, int last,
        const float* __restrict__ dW1, const float* __restrict__ db1,
        const float* __restrict__ dW2, const float* __restrict__ db2,
        float* __restrict__ out) {
    __shared__ float wsT [32 * 68];   // node W transposed: wsT[c*68 + k], k in [0,64)
    __shared__ float ws2T[32 * 68];   // next-step eW rows 32..95 transposed (or dec_W1)
    __shared__ float sv  [8 * 64];    // per-warp staging: [0:32) av, [32:64) hn
    __shared__ float prm [96];

    for (int i = threadIdx.x; i < 2048; i += 256) {
        int k = i >> 5, c = i & 31;
        wsT[c * 68 + k] = nW[i];
        if (last) { if (i < 1024) ws2T[c * 68 + k] = dW1[i]; }
        else        ws2T[c * 68 + k] = eW_next[32 * 32 + i];
    }
    if (threadIdx.x < 32) {
        prm[threadIdx.x]      = nb[threadIdx.x];
        prm[32 + threadIdx.x] = lns[threadIdx.x];
        prm[64 + threadIdx.x] = lnb[threadIdx.x];
    }
    __syncthreads();
    int lane = threadIdx.x & 31;
    int wslot = (threadIdx.x >> 5) * 64;
    int warp = (blockIdx.x * blockDim.x + threadIdx.x) >> 5;
    int nwarps = (gridDim.x * blockDim.x) >> 5;
    float bias = prm[lane], sc = prm[32 + lane], bi = prm[64 + lane];

    for (int n = warp; n < N_NODES; n += nwarps) {
        float av = g_agg[n * 32 + lane] * g_inv[n];
        g_agg[n * 32 + lane] = 0.f;          // ready for next step's edge_update
        float hv = g_h[n * 32 + lane];       // brings row into L1
        sv[wslot + lane] = av;
        __syncwarp();

        float acc = bias, acb = 0.f;
#pragma unroll
        for (int k4 = 0; k4 < 8; k4++) {
            float4 hb = *(const float4*)&g_h[n * 32 + k4 * 4];   // uniform broadcast, L1-hit
            float4 ab = *(const float4*)&sv[wslot + k4 * 4];     // broadcast LDS.128
            const float* wr = &wsT[lane * 68 + k4 * 4];
            float4 w1 = *(const float4*)wr;
            float4 w2 = *(const float4*)(wr + 32);
            acc += hb.x * w1.x + ab.x * w2.x;
            acb += hb.y * w1.y + ab.y * w2.y;
            acc += hb.z * w1.z + ab.z * w2.z;
            acb += hb.w * w1.w + ab.w * w2.w;
        }
        float m = leaky(acc + acb);
        float sm = m, qq = m * m;
#pragma unroll
        for (int d = 16; d; d >>= 1) {
            sm += __shfl_xor_sync(0xffffffffu, sm, d);
            qq += __shfl_xor_sync(0xffffffffu, qq, d);
        }
        float mu = sm * (1.f / 32.f);
        float var = fmaxf(qq * (1.f / 32.f) - mu * mu, 0.f);
        float hn = hv + (m - mu) * rsqrtf(var + LN_EPS) * sc + bi;
        g_h[n * 32 + lane] = hn;
        sv[wslot + 32 + lane] = hn;
        __syncwarp();

        if (!last) {
            float aS = 0.f, aD = 0.f;
#pragma unroll
            for (int k4 = 0; k4 < 8; k4++) {
                float4 hb = *(const float4*)&sv[wslot + 32 + k4 * 4];
                const float* wr = &ws2T[lane * 68 + k4 * 4];
                float4 w1 = *(const float4*)wr;
                float4 w2 = *(const float4*)(wr + 32);
                aS += hb.x * w1.x; aD += hb.x * w2.x;
                aS += hb.y * w1.y; aD += hb.y * w2.y;
                aS += hb.z * w1.z; aD += hb.z * w2.z;
                aS += hb.w * w1.w; aD += hb.w * w2.w;
            }
            g_hs[n * 32 + lane] = aS;
            g_hd[n * 32 + lane] = aD;
        } else {
            float t = db1[lane];
#pragma unroll
            for (int k4 = 0; k4 < 8; k4++) {
                float4 hb = *(const float4*)&sv[wslot + 32 + k4 * 4];
                float4 w1 = *(const float4*)&ws2T[lane * 68 + k4 * 4];
                t += hb.x * w1.x + hb.y * w1.y + hb.z * w1.z + hb.w * w1.w;
            }
            t = leaky(t) * dW2[lane];
#pragma unroll
            for (int d = 16; d; d >>= 1)
                t += __shfl_xor_sync(0xffffffffu, t, d);
            if (lane == 0) out[n] = t + db2[0];
        }
        __syncwarp();
    }
}

// ================= launch =================
extern "C" void kernel_launch(void* const* d_in, const int* in_sizes, int n_in,
                              void* d_out, int out_size) {
    const float* x   = (const float*)d_in[0];
    const float* ea  = (const float*)d_in[1];
    const int*   snd = (const int*)d_in[2];
    const int*   rcv = (const int*)d_in[3];
    const float* neW = (const float*)d_in[4];
    const float* neb = (const float*)d_in[5];
    const float* eeW = (const float*)d_in[6];
    const float* eeb = (const float*)d_in[7];
    const float* eW  = (const float*)d_in[8];
    const float* eb  = (const float*)d_in[9];
    const float* els = (const float*)d_in[10];
    const float* elb = (const float*)d_in[11];
    const float* nW  = (const float*)d_in[12];
    const float* nb  = (const float*)d_in[13];
    const float* nls = (const float*)d_in[14];
    const float* nlb = (const float*)d_in[15];
    const float* dW1 = (const float*)d_in[16];
    const float* db1 = (const float*)d_in[17];
    const float* dW2 = (const float*)d_in[18];
    const float* db2 = (const float*)d_in[19];
    float* out = (float*)d_out;

    hist_edges<<<(N_EDGES + 255) / 256, 256>>>(rcv);
    scan_all<<<1, 1024>>>();
    fused_encode<<<ENC_EDGE_BLOCKS + ENC_NODE_BLOCKS, 256>>>(
        ea, snd, rcv, eeW, eeb, x, neW, neb, eW);

    for (int s = 0; s < STEPS; s++) {
        edge_update<<<EDGE_BLOCKS, 256>>>(eW + s * 96 * 32, eb + s * 32,
                                          els + s * 32, elb + s * 32);
        int last = (s == STEPS - 1);
        node_update<<<NODE_BLOCKS, 256>>>(nW + s * 64 * 32, nb + s * 32,
                                          nls + s * 32, nlb + s * 32,
                                          eW + (s + 1 < STEPS ? (s + 1) * 96 * 32 : 0), last,
                                          dW1, db1, dW2, db2, out);
    }
}